// round 13
// baseline (speedup 1.0000x reference)
#include <cuda_runtime.h>
#include <cstdint>
#include <math.h>

#define SEQ   2048
#define BATCH 64
#define INP   256
#define HID   256

typedef unsigned long long ull;

// ---------- packed f32x2 helpers (Blackwell FFMA2 path, PTX-only) ----------
__device__ __forceinline__ void ffma2(ull& d, ull a, ull b) {
    asm("fma.rn.f32x2 %0, %1, %2, %0;" : "+l"(d) : "l"(a), "l"(b));
}
__device__ __forceinline__ ull pk(float a, float b) {
    ull r; asm("mov.b64 %0, {%1, %2};" : "=l"(r) : "f"(a), "f"(b)); return r;
}
__device__ __forceinline__ ull pku(unsigned a, unsigned b) {
    ull r; asm("mov.b64 %0, {%1, %2};" : "=l"(r) : "r"(a), "r"(b)); return r;
}
__device__ __forceinline__ float2 unpk(ull v) {
    float x, y; asm("mov.b64 {%0, %1}, %2;" : "=f"(x), "=f"(y) : "l"(v));
    return make_float2(x, y);
}
__device__ __forceinline__ unsigned smem_u32(const void* p) {
    unsigned a;
    asm("{ .reg .u64 t; cvta.to.shared.u64 t, %1; cvt.u32.u64 %0, t; }"
        : "=r"(a) : "l"(p));
    return a;
}
__device__ __forceinline__ unsigned mapa_rank(unsigned local_addr, unsigned rank) {
    unsigned r;
    asm("mapa.shared::cluster.u32 %0, %1, %2;" : "=r"(r) : "r"(local_addr), "r"(rank));
    return r;
}
// Branch-free tanh: 1 - 2/(e^{2x}+1). ex2/rcp approx, abs err ~1e-7.
__device__ __forceinline__ float fast_tanh(float x) {
    float e;
    asm("ex2.approx.ftz.f32 %0, %1;" : "=f"(e) : "f"(x * 2.8853900817779268f));
    float r;
    asm("rcp.approx.ftz.f32 %0, %1;" : "=f"(r) : "f"(e + 1.0f));
    return fmaf(-2.0f, r, 1.0f);
}

// =====================================================================
// Phase 1: xp[t,b,h] = x[t,b]·W_ih[h] + b_ih[h] + b_hh[h]  (unchanged)
// =====================================================================
__global__ __launch_bounds__(256) void xp_gemm_kernel(
    const float* __restrict__ x,
    const float* __restrict__ Wih,
    const float* __restrict__ bih,
    const float* __restrict__ bhh,
    float* __restrict__ out)
{
    __shared__ float Xs[32][68];
    __shared__ float Ws[32][257];

    const int t   = blockIdx.x;
    const int tid = threadIdx.x;
    const int tn  = tid & 31;
    const int tm  = tid >> 5;
    const int m0  = tm * 8;

    const float* xt = x + (size_t)t * BATCH * INP;

    ull acc[8][4];
    #pragma unroll
    for (int u = 0; u < 8; ++u)
        #pragma unroll
        for (int v = 0; v < 4; ++v) acc[u][v] = 0ull;

    for (int kc = 0; kc < INP; kc += 32) {
        #pragma unroll
        for (int r = 0; r < 2; ++r) {
            int idx = tid + 256 * r;
            int m   = idx >> 3;
            int k4  = (idx & 7) * 4;
            float4 v = *(const float4*)(xt + (size_t)m * INP + kc + k4);
            Xs[k4 + 0][m] = v.x; Xs[k4 + 1][m] = v.y;
            Xs[k4 + 2][m] = v.z; Xs[k4 + 3][m] = v.w;
        }
        #pragma unroll
        for (int r = 0; r < 8; ++r) {
            int idx = tid + 256 * r;
            int h   = idx >> 3;
            int k4  = (idx & 7) * 4;
            float4 v = *(const float4*)(Wih + (size_t)h * INP + kc + k4);
            Ws[k4 + 0][h] = v.x; Ws[k4 + 1][h] = v.y;
            Ws[k4 + 2][h] = v.z; Ws[k4 + 3][h] = v.w;
        }
        __syncthreads();

        #pragma unroll
        for (int k = 0; k < 32; ++k) {
            float4 a0 = *(const float4*)&Xs[k][m0];
            float4 a1 = *(const float4*)&Xs[k][m0 + 4];
            ull ap[8];
            ap[0] = pk(a0.x, a0.x); ap[1] = pk(a0.y, a0.y);
            ap[2] = pk(a0.z, a0.z); ap[3] = pk(a0.w, a0.w);
            ap[4] = pk(a1.x, a1.x); ap[5] = pk(a1.y, a1.y);
            ap[6] = pk(a1.z, a1.z); ap[7] = pk(a1.w, a1.w);

            float w[8];
            #pragma unroll
            for (int v = 0; v < 8; ++v) w[v] = Ws[k][tn + 32 * v];

            #pragma unroll
            for (int v2 = 0; v2 < 4; ++v2) {
                ull wp = pk(w[2 * v2], w[2 * v2 + 1]);
                #pragma unroll
                for (int u = 0; u < 8; ++u)
                    ffma2(acc[u][v2], wp, ap[u]);
            }
        }
        __syncthreads();
    }

    float ba[4], bb[4];
    #pragma unroll
    for (int v2 = 0; v2 < 4; ++v2) {
        int hA = tn + 64 * v2, hB = hA + 32;
        ba[v2] = bih[hA] + bhh[hA];
        bb[v2] = bih[hB] + bhh[hB];
    }
    float* ot = out + (size_t)t * BATCH * HID;
    #pragma unroll
    for (int u = 0; u < 8; ++u) {
        float* row = ot + (size_t)(m0 + u) * HID;
        #pragma unroll
        for (int v2 = 0; v2 < 4; ++v2) {
            float2 s = unpk(acc[u][v2]);
            row[tn + 64 * v2]      = s.x + ba[v2];
            row[tn + 64 * v2 + 32] = s.y + bb[v2];
        }
    }
}

// =====================================================================
// Phase 2: serial scan, v11 — cluster-4, 2 batches, pure dataflow.
// grid 128 = 32 clusters x 4 CTAs. Cluster c: batches {2c, 2c+1};
// CTA rank rk owns rows [64rk,+64) of BOTH batches, full 256 k.
// Warps 0-7 = batch-A engine, 8-15 = batch-B engine (independent
// serial loops; B's compute fills A's transit window and vice versa).
// Warp wl (in group): rows 8wl..+8; lane: row = 64rk+8wl+(l>>2),
// kwin = l&3 -> k in [64*kwin,+64), W = 32 ull regs.
// ALL h as {f32,seq} u64 pairs, replicated per CTA per batch per
// parity (4 windows x 66-ull padded stride -> conflict-free LDS.128).
// Finalizer (kwin0) stores self pair + 3 remote (st.shared::cluster).
// NO barriers/fences in the loop: the all-to-all row dependence each
// step bounds warp skew to 1 step (a warp's t+2 poll needs every
// warp's t+1 send, which follows that warp's t+1 reads) -> slot
// overwrite cannot precede consumption.
// =====================================================================
#define WPRS 66                      // u64 stride per 64-slot window
#define PARB (4 * WPRS * 8)          // parity block bytes (2112)
#define GRPB (2 * PARB)              // group (batch) block bytes (4224)

__global__ __launch_bounds__(512, 1) __cluster_dims__(4, 1, 1)
void rnn_scan_kernel(
    const float* __restrict__ Whh,  // [HID][HID]
    float* __restrict__ out)        // in: xp, out: h   [SEQ][BATCH][HID]
{
    __shared__ alignas(16) ull pairs[2][2][4 * WPRS];   // [gb][parity][.] 8448B

    const int bidx = blockIdx.x;
    const int rk   = bidx & 3;              // cluster rank
    const int bA   = (bidx >> 2) * 2;       // batch A of this cluster
    const int tid  = threadIdx.x;
    const int l    = tid & 31;
    const int w    = tid >> 5;
    const int gb   = w >> 3;                // 0 = batch A engine, 1 = B
    const int wl   = w & 7;                 // warp within group
    const int kwin = l & 3;                 // k-window of 64
    const int j    = 64 * rk + 8 * wl + (l >> 2);   // global row [0,256)
    const int b    = bA + gb;               // my batch

    // ---- register-resident W: W_hh[j][64*kwin + 0..63] ----
    ull wreg[32];
    {
        const float* wrow = Whh + (size_t)j * HID + 64 * kwin;
        #pragma unroll
        for (int p = 0; p < 32; ++p)
            wreg[p] = *(const ull*)(wrow + 2 * p);
    }

    // ---- init: all slots {val=0, seq=0} (h_{-1}=0, matches t=0 poll) ----
    for (int i = tid; i < 2 * 2 * 4 * WPRS; i += 512)
        ((ull*)pairs)[i] = 0ull;
    __syncthreads();
    asm volatile("barrier.cluster.arrive.aligned;" ::: "memory");
    asm volatile("barrier.cluster.wait.aligned;"   ::: "memory");

    // ---- addresses ----
    const unsigned gbase = smem_u32(pairs) + (unsigned)gb * GRPB;  // my group base
    unsigned peerb[3];
    #pragma unroll
    for (int c = 0; c < 3; ++c)
        peerb[c] = mapa_rank(gbase, (unsigned)((rk + 1 + c) & 3));

    // my send slot offset (within a parity block)
    const unsigned sloff = (unsigned)(WPRS * (j >> 6) + (j & 63)) * 8u;
    // poll offsets: lane validates slots l+32c, c=0..7
    unsigned poff[8];
    #pragma unroll
    for (int c = 0; c < 8; ++c) {
        int s = l + 32 * c;
        poff[c] = (unsigned)(WPRS * (s >> 6) + (s & 63)) * 8u;
    }

    const size_t stride = (size_t)BATCH * HID;
    float* col = out + (size_t)b * HID + j;

    // xp queue depth 2 (only kwin 0/1 lanes use it)
    float xq0 = 0.f, xq1 = 0.f;
    if (kwin < 2) {
        xq0 = __ldcg(col);
        xq1 = __ldcg(col + stride);
    }

    for (int t = 0; t < SEQ; ++t) {
        const unsigned sp = (unsigned)(t & 1);   // store parity (h_t)
        const unsigned rp = sp ^ 1u;             // read parity (h_{t-1})

        // ---- poll: all 256 slots of my group's read parity ----
        {
            const unsigned base = gbase + rp * (unsigned)PARB;
            const unsigned T = (unsigned)t;
            unsigned ok;
            do {
                ull v0, v1, v2, v3, v4, v5, v6, v7;
                asm volatile("ld.volatile.shared.u64 %0, [%1];" : "=l"(v0) : "r"(base + poff[0]) : "memory");
                asm volatile("ld.volatile.shared.u64 %0, [%1];" : "=l"(v1) : "r"(base + poff[1]) : "memory");
                asm volatile("ld.volatile.shared.u64 %0, [%1];" : "=l"(v2) : "r"(base + poff[2]) : "memory");
                asm volatile("ld.volatile.shared.u64 %0, [%1];" : "=l"(v3) : "r"(base + poff[3]) : "memory");
                asm volatile("ld.volatile.shared.u64 %0, [%1];" : "=l"(v4) : "r"(base + poff[4]) : "memory");
                asm volatile("ld.volatile.shared.u64 %0, [%1];" : "=l"(v5) : "r"(base + poff[5]) : "memory");
                asm volatile("ld.volatile.shared.u64 %0, [%1];" : "=l"(v6) : "r"(base + poff[6]) : "memory");
                asm volatile("ld.volatile.shared.u64 %0, [%1];" : "=l"(v7) : "r"(base + poff[7]) : "memory");
                ok = ((unsigned)(v0 >> 32) == T) & ((unsigned)(v1 >> 32) == T)
                   & ((unsigned)(v2 >> 32) == T) & ((unsigned)(v3 >> 32) == T)
                   & ((unsigned)(v4 >> 32) == T) & ((unsigned)(v5 >> 32) == T)
                   & ((unsigned)(v6 >> 32) == T) & ((unsigned)(v7 >> 32) == T);
            } while (__all_sync(0xFFFFFFFFu, ok) == 0);
        }

        // ---- matvec over my 64 k-values: 32 LDS.128 + 32 ffma2 ----
        const uint4* pq = (const uint4*)((const char*)pairs
                           + gb * GRPB + (int)rp * PARB + kwin * (WPRS * 8));
        ull a0 = 0ull, a1 = 0ull, a2 = 0ull, a3 = 0ull;
        #pragma unroll
        for (int m = 0; m < 32; m += 4) {
            uint4 u0 = pq[m + 0];    // slots {h,s}{h,s}
            uint4 u1 = pq[m + 1];
            uint4 u2 = pq[m + 2];
            uint4 u3 = pq[m + 3];
            ffma2(a0, wreg[m + 0], pku(u0.x, u0.z));
            ffma2(a1, wreg[m + 1], pku(u1.x, u1.z));
            ffma2(a2, wreg[m + 2], pku(u2.x, u2.z));
            ffma2(a3, wreg[m + 3], pku(u3.x, u3.z));
        }
        float2 s0 = unpk(a0), s1 = unpk(a1), s2 = unpk(a2), s3 = unpk(a3);
        float part = ((s0.x + s0.y) + (s1.x + s1.y))
                   + ((s2.x + s2.y) + (s3.x + s3.y));

        // ---- quad combine (kwin 0..3 of one row) ----
        part += __shfl_xor_sync(0xFFFFFFFFu, part, 1);
        part += __shfl_xor_sync(0xFFFFFFFFu, part, 2);

        float val = fast_tanh(xq0 + part);   // branchless, all lanes

        if (kwin == 0 && t + 1 < SEQ) {
            // publish h_t: self + 3 remote CTAs (u64 atomic, seq-validated)
            ull hv = pku(__float_as_uint(val), (unsigned)(t + 1));
            const unsigned off = sp * (unsigned)PARB + sloff;
            asm volatile("st.shared.u64 [%0], %1;"
                         :: "r"(gbase + off), "l"(hv) : "memory");
            asm volatile("st.shared::cluster.u64 [%0], %1;"
                         :: "r"(peerb[0] + off), "l"(hv) : "memory");
            asm volatile("st.shared::cluster.u64 [%0], %1;"
                         :: "r"(peerb[1] + off), "l"(hv) : "memory");
            asm volatile("st.shared::cluster.u64 [%0], %1;"
                         :: "r"(peerb[2] + off), "l"(hv) : "memory");
        }
        if (kwin == 1) {
            col[(size_t)t * stride] = val;   // h_t -> gmem
        }
        if (kwin < 2) {
            xq0 = xq1;
            if (t + 2 < SEQ) xq1 = __ldcg(col + (size_t)(t + 2) * stride);
        }
    }

    asm volatile("barrier.cluster.arrive.aligned;" ::: "memory");
    asm volatile("barrier.cluster.wait.aligned;"   ::: "memory");
}

// =====================================================================
extern "C" void kernel_launch(void* const* d_in, const int* in_sizes, int n_in,
                              void* d_out, int out_size) {
    const float* x   = (const float*)d_in[0];  // [SEQ][BATCH][INP]
    const float* Wih = (const float*)d_in[1];  // [HID][INP]
    const float* Whh = (const float*)d_in[2];  // [HID][HID]
    const float* bih = (const float*)d_in[3];  // [HID]
    const float* bhh = (const float*)d_in[4];  // [HID]
    float* out = (float*)d_out;                // [SEQ][BATCH][HID]

    xp_gemm_kernel<<<SEQ, 256>>>(x, Wih, bih, bhh, out);
    rnn_scan_kernel<<<2 * BATCH, 512>>>(Whh, out);
}

// round 14
// speedup vs baseline: 1.5157x; 1.5157x over previous
#include <cuda_runtime.h>
#include <cstdint>
#include <math.h>

#define SEQ   2048
#define BATCH 64
#define INP   256
#define HID   256

typedef unsigned long long ull;

// ---------- packed f32x2 helpers (Blackwell FFMA2 path, PTX-only) ----------
__device__ __forceinline__ void ffma2(ull& d, ull a, ull b) {
    asm("fma.rn.f32x2 %0, %1, %2, %0;" : "+l"(d) : "l"(a), "l"(b));
}
__device__ __forceinline__ ull pk(float a, float b) {
    ull r; asm("mov.b64 %0, {%1, %2};" : "=l"(r) : "f"(a), "f"(b)); return r;
}
__device__ __forceinline__ ull pku(unsigned a, unsigned b) {
    ull r; asm("mov.b64 %0, {%1, %2};" : "=l"(r) : "r"(a), "r"(b)); return r;
}
__device__ __forceinline__ float2 unpk(ull v) {
    float x, y; asm("mov.b64 {%0, %1}, %2;" : "=f"(x), "=f"(y) : "l"(v));
    return make_float2(x, y);
}
__device__ __forceinline__ unsigned smem_u32(const void* p) {
    unsigned a;
    asm("{ .reg .u64 t; cvta.to.shared.u64 t, %1; cvt.u32.u64 %0, t; }"
        : "=r"(a) : "l"(p));
    return a;
}
__device__ __forceinline__ unsigned mapa_peer(unsigned local_addr, unsigned peer) {
    unsigned r;
    asm("mapa.shared::cluster.u32 %0, %1, %2;" : "=r"(r) : "r"(local_addr), "r"(peer));
    return r;
}
// Branch-free tanh: 1 - 2/(e^{2x}+1). ex2/rcp approx, abs err ~1e-7.
__device__ __forceinline__ float fast_tanh(float x) {
    float e;
    asm("ex2.approx.ftz.f32 %0, %1;" : "=f"(e) : "f"(x * 2.8853900817779268f));
    float r;
    asm("rcp.approx.ftz.f32 %0, %1;" : "=f"(r) : "f"(e + 1.0f));
    return fmaf(-2.0f, r, 1.0f);
}

// =====================================================================
// Phase 1: xp[t,b,h] = x[t,b]·W_ih[h] + b_ih[h] + b_hh[h]  (unchanged)
// =====================================================================
__global__ __launch_bounds__(256) void xp_gemm_kernel(
    const float* __restrict__ x,
    const float* __restrict__ Wih,
    const float* __restrict__ bih,
    const float* __restrict__ bhh,
    float* __restrict__ out)
{
    __shared__ float Xs[32][68];
    __shared__ float Ws[32][257];

    const int t   = blockIdx.x;
    const int tid = threadIdx.x;
    const int tn  = tid & 31;
    const int tm  = tid >> 5;
    const int m0  = tm * 8;

    const float* xt = x + (size_t)t * BATCH * INP;

    ull acc[8][4];
    #pragma unroll
    for (int u = 0; u < 8; ++u)
        #pragma unroll
        for (int v = 0; v < 4; ++v) acc[u][v] = 0ull;

    for (int kc = 0; kc < INP; kc += 32) {
        #pragma unroll
        for (int r = 0; r < 2; ++r) {
            int idx = tid + 256 * r;
            int m   = idx >> 3;
            int k4  = (idx & 7) * 4;
            float4 v = *(const float4*)(xt + (size_t)m * INP + kc + k4);
            Xs[k4 + 0][m] = v.x; Xs[k4 + 1][m] = v.y;
            Xs[k4 + 2][m] = v.z; Xs[k4 + 3][m] = v.w;
        }
        #pragma unroll
        for (int r = 0; r < 8; ++r) {
            int idx = tid + 256 * r;
            int h   = idx >> 3;
            int k4  = (idx & 7) * 4;
            float4 v = *(const float4*)(Wih + (size_t)h * INP + kc + k4);
            Ws[k4 + 0][h] = v.x; Ws[k4 + 1][h] = v.y;
            Ws[k4 + 2][h] = v.z; Ws[k4 + 3][h] = v.w;
        }
        __syncthreads();

        #pragma unroll
        for (int k = 0; k < 32; ++k) {
            float4 a0 = *(const float4*)&Xs[k][m0];
            float4 a1 = *(const float4*)&Xs[k][m0 + 4];
            ull ap[8];
            ap[0] = pk(a0.x, a0.x); ap[1] = pk(a0.y, a0.y);
            ap[2] = pk(a0.z, a0.z); ap[3] = pk(a0.w, a0.w);
            ap[4] = pk(a1.x, a1.x); ap[5] = pk(a1.y, a1.y);
            ap[6] = pk(a1.z, a1.z); ap[7] = pk(a1.w, a1.w);

            float w[8];
            #pragma unroll
            for (int v = 0; v < 8; ++v) w[v] = Ws[k][tn + 32 * v];

            #pragma unroll
            for (int v2 = 0; v2 < 4; ++v2) {
                ull wp = pk(w[2 * v2], w[2 * v2 + 1]);
                #pragma unroll
                for (int u = 0; u < 8; ++u)
                    ffma2(acc[u][v2], wp, ap[u]);
            }
        }
        __syncthreads();
    }

    float ba[4], bb[4];
    #pragma unroll
    for (int v2 = 0; v2 < 4; ++v2) {
        int hA = tn + 64 * v2, hB = hA + 32;
        ba[v2] = bih[hA] + bhh[hA];
        bb[v2] = bih[hB] + bhh[hB];
    }
    float* ot = out + (size_t)t * BATCH * HID;
    #pragma unroll
    for (int u = 0; u < 8; ++u) {
        float* row = ot + (size_t)(m0 + u) * HID;
        #pragma unroll
        for (int v2 = 0; v2 < 4; ++v2) {
            float2 s = unpk(acc[u][v2]);
            row[tn + 64 * v2]      = s.x + ba[v2];
            row[tn + 64 * v2 + 32] = s.y + bb[v2];
        }
    }
}

// =====================================================================
// Phase 2: serial scan, v12 — R8 topology, finalizer = g2 (remote-k).
// Cluster {2b,2b+1}; rank r finalizes rows [128r,+128) over all 256 k.
// 512 threads: jj=tid&127 (row), g=tid>>7 (k-window of 64):
//   g0/g1: local k — matvec from hbuf immediately, publish partial
//          as {f32, seq=t+1} pair (ready LONG before needed)
//   g3   : peer k hi — poll remote h pairs, matvec, publish pair
//   g2   : peer k lo — poll remote h pairs, matvec, then poll the 3
//          partial pairs (all ~ready), tanh, SEND remote h pair,
//          write local hbuf, STG.  Finalize happens at the point the
//          last data exists — no STS+BAR+wakeup handoff to g0.
// One __syncthreads per step (orders hbuf + pair-slot reuse only).
// Remote h: {f32,seq} u64 pairs, parity double-buffered, no fences.
// =====================================================================
__global__ __launch_bounds__(512, 1) __cluster_dims__(2, 1, 1)
void rnn_scan_kernel(
    const float* __restrict__ Whh,  // [HID][HID]
    float* __restrict__ out)        // in: xp, out: h   [SEQ][BATCH][HID]
{
    __shared__ float hbuf[2][128];                 // local h by parity
    __shared__ alignas(16) ull pairbuf[2][128];    // peer h pairs by parity
    __shared__ alignas(16) ull ppair[2][3][128];   // partial pairs [par][src][jj]

    const int bidx = blockIdx.x;
    const int b    = bidx >> 1;
    const int r    = bidx & 1;             // cluster rank
    const int tid  = threadIdx.x;
    const int jj   = tid & 127;            // row within my half
    const int g    = tid >> 7;             // k-window group
    const int lane = tid & 31;
    const int j    = 128 * r + jj;         // global row

    const int koff = (g < 2) ? (128 * r + 64 * g)
                             : (128 * (1 - r) + 64 * (g - 2));

    // ---- register-resident W: W_hh[j][koff + 0..63] ----
    ull wreg[32];
    {
        const float* wrow = Whh + (size_t)j * HID + koff;
        #pragma unroll
        for (int p = 0; p < 32; ++p)
            wreg[p] = *(const ull*)(wrow + 2 * p);
    }

    // ---- init smem ----
    if (tid < 256) ((float*)hbuf)[tid] = 0.f;
    if (tid < 256) ((ull*)pairbuf)[tid] = 0ull;    // seq=0 matches t=0 poll
    for (int i = tid; i < 768; i += 512) ((ull*)ppair)[i] = 0ull;
    __syncthreads();
    asm volatile("barrier.cluster.arrive.aligned;" ::: "memory");
    asm volatile("barrier.cluster.wait.aligned;"   ::: "memory");

    const unsigned peer      = (unsigned)(r ^ 1);
    const unsigned pair_l    = smem_u32(pairbuf);
    const unsigned ppair_l   = smem_u32(ppair);
    const unsigned peer_pair = mapa_peer(pair_l, peer);

    const size_t stride = (size_t)BATCH * HID;
    float* col = out + (size_t)b * HID + j;

    // xp prefetch queue, depth 2 (g2 = finalizer holds it)
    float xq0 = 0.f, xq1 = 0.f;
    if (g == 2) {
        xq0 = __ldcg(col);
        xq1 = __ldcg(col + stride);
    }

    for (int t = 0; t < SEQ; ++t) {
        const unsigned sp = (unsigned)(t & 1);   // publish parity
        const unsigned rp = sp ^ 1u;             // read parity
        const unsigned T1 = (unsigned)(t + 1);

        // g2: hoist next xp load above everything (independent)
        float xq2 = 0.f;
        if (g == 2 && t + 2 < SEQ)
            xq2 = __ldcg(col + (size_t)(t + 2) * stride);

        // ---- matvec partial over my 64 k-values ----
        ull a0 = 0ull, a1 = 0ull, a2 = 0ull, a3 = 0ull;
        if (g < 2) {
            const ulonglong2* h2 =
                (const ulonglong2*)&hbuf[rp][64 * g];
            #pragma unroll
            for (int q = 0; q < 16; ++q) {
                ulonglong2 h = h2[q];
                if (q & 1) { ffma2(a2, wreg[2 * q],     h.x);
                             ffma2(a3, wreg[2 * q + 1], h.y); }
                else       { ffma2(a0, wreg[2 * q],     h.x);
                             ffma2(a1, wreg[2 * q + 1], h.y); }
            }
        } else {
            // peer h: warp-collective seqno validation, then bulk pair reads
            const unsigned base = pair_l + rp * 1024u
                                         + (unsigned)(g - 2) * 512u;
            const unsigned aA = base + (unsigned)lane * 8u;
            const unsigned aB = aA + 256u;
            const unsigned T  = (unsigned)t;
            unsigned ok;
            do {
                ull p1, p2;
                asm volatile("ld.volatile.shared.u64 %0, [%1];"
                             : "=l"(p1) : "r"(aA) : "memory");
                asm volatile("ld.volatile.shared.u64 %0, [%1];"
                             : "=l"(p2) : "r"(aB) : "memory");
                ok = ((unsigned)(p1 >> 32) == T) & ((unsigned)(p2 >> 32) == T);
            } while (__all_sync(0xFFFFFFFFu, ok) == 0);

            const uint4* pq = (const uint4*)((const char*)pairbuf
                               + (int)rp * 1024 + (g - 2) * 512);
            #pragma unroll
            for (int q = 0; q < 16; ++q) {
                uint4 vA = pq[2 * q];        // {h0,s0,h1,s1}
                uint4 vB = pq[2 * q + 1];
                if (q & 1) { ffma2(a2, wreg[2 * q],     pku(vA.x, vA.z));
                             ffma2(a3, wreg[2 * q + 1], pku(vB.x, vB.z)); }
                else       { ffma2(a0, wreg[2 * q],     pku(vA.x, vA.z));
                             ffma2(a1, wreg[2 * q + 1], pku(vB.x, vB.z)); }
            }
        }
        float2 s0 = unpk(a0), s1 = unpk(a1), s2 = unpk(a2), s3 = unpk(a3);
        float part = ((s0.x + s0.y) + (s1.x + s1.y))
                   + ((s2.x + s2.y) + (s3.x + s3.y));

        if (g != 2) {
            // publish partial pair {part, t+1}; src idx: g0->0, g1->1, g3->2
            const int src = (g < 2) ? g : 2;
            ull pv = pku(__float_as_uint(part), T1);
            unsigned pa = ppair_l + sp * 3072u
                                  + (unsigned)src * 1024u
                                  + (unsigned)jj * 8u;
            asm volatile("st.volatile.shared.u64 [%0], %1;"
                         :: "r"(pa), "l"(pv) : "memory");
        } else {
            // ---- g2 finalizes: poll 3 partial pairs (all ~ready) ----
            const unsigned pa = ppair_l + sp * 3072u + (unsigned)jj * 8u;
            ull v1, v2, v3;
            unsigned ok;
            do {
                asm volatile("ld.volatile.shared.u64 %0, [%1];"
                             : "=l"(v1) : "r"(pa) : "memory");
                asm volatile("ld.volatile.shared.u64 %0, [%1];"
                             : "=l"(v2) : "r"(pa + 1024u) : "memory");
                asm volatile("ld.volatile.shared.u64 %0, [%1];"
                             : "=l"(v3) : "r"(pa + 2048u) : "memory");
                ok = ((unsigned)(v1 >> 32) == T1)
                   & ((unsigned)(v2 >> 32) == T1)
                   & ((unsigned)(v3 >> 32) == T1);
            } while (!ok);

            float sum = part
                      + (__uint_as_float((unsigned)v1)
                      +  __uint_as_float((unsigned)v2))
                      +  __uint_as_float((unsigned)v3);
            float val = fast_tanh(xq0 + sum);

            // 1) remote h pair FIRST (starts transit earliest)
            if (t + 1 < SEQ) {
                ull hv = pku(__float_as_uint(val), T1);
                asm volatile("st.shared::cluster.u64 [%0], %1;"
                             :: "r"(peer_pair + sp * 1024u
                                              + (unsigned)jj * 8u),
                                "l"(hv) : "memory");
            }
            // 2) local h (ordered by the bar.sync below)
            hbuf[sp][jj] = val;
            // 3) output
            col[(size_t)t * stride] = val;
            // 4) advance xp queue
            xq0 = xq1;
            xq1 = xq2;
        }

        __syncthreads();   // single per-step barrier: hbuf/slot-reuse order
    }

    asm volatile("barrier.cluster.arrive.aligned;" ::: "memory");
    asm volatile("barrier.cluster.wait.aligned;"   ::: "memory");
}

// =====================================================================
extern "C" void kernel_launch(void* const* d_in, const int* in_sizes, int n_in,
                              void* d_out, int out_size) {
    const float* x   = (const float*)d_in[0];  // [SEQ][BATCH][INP]
    const float* Wih = (const float*)d_in[1];  // [HID][INP]
    const float* Whh = (const float*)d_in[2];  // [HID][HID]
    const float* bih = (const float*)d_in[3];  // [HID]
    const float* bhh = (const float*)d_in[4];  // [HID]
    float* out = (float*)d_out;                // [SEQ][BATCH][HID]

    xp_gemm_kernel<<<SEQ, 256>>>(x, Wih, bih, bhh, out);
    rnn_scan_kernel<<<2 * BATCH, 512>>>(Whh, out);
}